// round 8
// baseline (speedup 1.0000x reference)
#include <cuda_runtime.h>
#include <cuda_bf16.h>

constexpr int B_ROWS  = 1024;
constexpr int L_COLS  = 4096;
constexpr int THREADS = 256;               // threads per row-block
constexpr int PER     = L_COLS / THREADS;  // 16 elements per thread
constexpr float INV_TAU = 1.0f / 0.85f;
constexpr float A_COEF  = 2.0f * INV_TAU;  // r = A*c/(k+T)

__device__ float g_row[B_ROWS];
__device__ unsigned int g_counter;   // zero-init; self-resetting

// occ=7: 148*7 = 1036 >= 1024 -> ALL row-blocks resident, single wave
__global__ __launch_bounds__(THREADS, 7)
void divloss_fused_kernel(const float* __restrict__ p_in,
                          const int*   __restrict__ lab_in,
                          float*       __restrict__ out) {
    const int row  = blockIdx.x;
    const int t    = threadIdx.x;
    const int lane = t & 31;
    const int warp = t >> 5;

    const int4*   lab = reinterpret_cast<const int4*>(lab_in + (size_t)row * L_COLS) + t * 4;
    const float4* pv  = reinterpret_cast<const float4*>(p_in  + (size_t)row * L_COLS) + t * 4;

    // ---- front-batched streaming loads (8x LDG.128, MLP=8) ----
    int4   l0 = __ldcs(lab + 0), l1 = __ldcs(lab + 1),
           l2 = __ldcs(lab + 2), l3 = __ldcs(lab + 3);
    float4 p0 = __ldcs(pv + 0),  p1 = __ldcs(pv + 1),
           p2 = __ldcs(pv + 2),  p3 = __ldcs(pv + 3);

    // pack 16 binary labels into one bitmask
    unsigned bits =
         (unsigned)l0.x        | ((unsigned)l0.y << 1)  | ((unsigned)l0.z << 2)  | ((unsigned)l0.w << 3)
      | ((unsigned)l1.x << 4)  | ((unsigned)l1.y << 5)  | ((unsigned)l1.z << 6)  | ((unsigned)l1.w << 7)
      | ((unsigned)l2.x << 8)  | ((unsigned)l2.y << 9)  | ((unsigned)l2.z << 10) | ((unsigned)l2.w << 11)
      | ((unsigned)l3.x << 12) | ((unsigned)l3.y << 13) | ((unsigned)l3.z << 14) | ((unsigned)l3.w << 15);
    const int local = __popc(bits);

    // ---- warp inclusive scan of per-thread label counts ----
    int x = local;
#pragma unroll
    for (int o = 1; o < 32; o <<= 1) {
        int y = __shfl_up_sync(0xffffffffu, x, o);
        if (lane >= o) x += y;
    }
    __shared__ int s_warp[8];
    if (lane == 31) s_warp[warp] = x;

    // ---- hoisted: compute log(p) NOW, overlapping the load/scan latency ----
    float lp[PER] = { p0.x, p0.y, p0.z, p0.w, p1.x, p1.y, p1.z, p1.w,
                      p2.x, p2.y, p2.z, p2.w, p3.x, p3.y, p3.z, p3.w };
#pragma unroll
    for (int i = 0; i < PER; ++i) lp[i] = __logf(lp[i]);

    __syncthreads();   // the ONLY pre-compute barrier

    // ---- raking: every thread reads the 8 warp sums (broadcast LDS) ----
    int off = 0, tot = 0;
#pragma unroll
    for (int w = 0; w < 8; ++w) {
        int s = s_warp[w];
        tot += s;
        if (w < warp) off += s;
    }

    const float Tf = (float)tot;
    float cf = (float)(off + (x - local));        // exclusive prefix count
    const float d0 = (float)(t * PER + 1) + Tf;   // first denominator

    float s1 = 0.0f, s2 = 0.0f;
    if (d0 >= 1024.0f) {
        // one RCP per thread; 1/(d0+i) = inv0*(1 - x + x^2), x = i*inv0
        const float inv0 = __fdividef(1.0f, d0);
        const float b0   = A_COEF * inv0;
#pragma unroll
        for (int i = 0; i < PER; ++i) {
            cf += ((bits >> i) & 1) ? 1.0f : 0.0f;
            float xi   = (float)i * inv0;
            float corr = fmaf(xi, xi, 1.0f) - xi;
            float r    = (cf * corr) * b0;
            float e    = __expf(r);
            s1 += e;
            s2  = fmaf(e, r - lp[i], s2);
        }
    } else {
        // rare small-T path: exact per-element divide
#pragma unroll
        for (int i = 0; i < PER; ++i) {
            cf += ((bits >> i) & 1) ? 1.0f : 0.0f;
            float r = __fdividef(A_COEF * cf, d0 + (float)i);
            float e = __expf(r);
            s1 += e;
            s2  = fmaf(e, r - lp[i], s2);
        }
    }

    // ---- block reduce (s1, s2) over 8 warps ----
#pragma unroll
    for (int o = 16; o; o >>= 1) {
        s1 += __shfl_down_sync(0xffffffffu, s1, o);
        s2 += __shfl_down_sync(0xffffffffu, s2, o);
    }
    __shared__ float r1[8], r2[8];
    if (lane == 0) { r1[warp] = s1; r2[warp] = s2; }
    __syncthreads();

    __shared__ bool s_last;
    if (t == 0) {
        float a1 = 0.0f, a2 = 0.0f;
#pragma unroll
        for (int w = 0; w < 8; ++w) { a1 += r1[w]; a2 += r2[w]; }
        g_row[row] = __fdividef(a2, a1) - __logf(a1);
        __threadfence();
        unsigned done = atomicAdd(&g_counter, 1u);
        s_last = (done == (unsigned)(B_ROWS - 1));
    }
    __syncthreads();

    // ---- last block: deterministic final reduction of all 1024 rows ----
    if (s_last) {
        if (t == 0) g_counter = 0;   // reset for graph replay
        float v = (g_row[t] + g_row[t + 256]) + (g_row[t + 512] + g_row[t + 768]);
#pragma unroll
        for (int o = 16; o; o >>= 1) v += __shfl_down_sync(0xffffffffu, v, o);
        __shared__ float sh[8];
        if (lane == 0) sh[warp] = v;
        __syncthreads();
        if (t == 0) {
            float w = 0.0f;
#pragma unroll
            for (int i = 0; i < 8; ++i) w += sh[i];
            out[0] = w * (1.0f / (float)B_ROWS);
        }
    }
}

extern "C" void kernel_launch(void* const* d_in, const int* in_sizes, int n_in,
                              void* d_out, int out_size) {
    const float* p_in   = (const float*)d_in[0];   // output: (B, L, 1) float32
    const int*   labels = (const int*)  d_in[1];   // labels: (B, L) int32
    float*       out    = (float*)d_out;

    divloss_fused_kernel<<<B_ROWS, THREADS>>>(p_in, labels, out);
}